// round 7
// baseline (speedup 1.0000x reference)
#include <cuda_runtime.h>
#include <cuda_bf16.h>

// Embedding gather: out[i, :] = table[ids[i], :]
// ids: int32 [819200], table: f32 [1e6, 32] (~128 MB; touched set ~72 MB, L2-resident),
// out: f32 [819200, 32]
//
//  - 256-bit (v8.b32) loads/stores: 32 B per thread per request (Blackwell native)
//  - table loads: ld.global.nc.L2::evict_last.v8 (inline form requires v8 on sm_103a)
//  - output stores: st.global.cs.v8 streaming (write-once; don't evict the table)
//  - 4 independent row-gathers per thread for memory-level parallelism

#define NSEG 4

struct U8 { unsigned r0,r1,r2,r3,r4,r5,r6,r7; };

__device__ __forceinline__ U8 ldg_table8(const void* p) {
    U8 v;
    asm volatile("ld.global.nc.L2::evict_last.v8.b32 {%0,%1,%2,%3,%4,%5,%6,%7}, [%8];"
                 : "=r"(v.r0), "=r"(v.r1), "=r"(v.r2), "=r"(v.r3),
                   "=r"(v.r4), "=r"(v.r5), "=r"(v.r6), "=r"(v.r7)
                 : "l"(p));
    return v;
}

__device__ __forceinline__ void stg_stream8(void* p, U8 v) {
    asm volatile("st.global.cs.v8.b32 [%0], {%1,%2,%3,%4,%5,%6,%7,%8};"
                 :: "l"(p),
                    "r"(v.r0), "r"(v.r1), "r"(v.r2), "r"(v.r3),
                    "r"(v.r4), "r"(v.r5), "r"(v.r6), "r"(v.r7)
                 : "memory");
}

__global__ void __launch_bounds__(256)
embedding_gather_kernel(const int* __restrict__ ids,
                        const char* __restrict__ table,
                        char* __restrict__ out,
                        int seg) {
    int i = blockIdx.x * blockDim.x + threadIdx.x;
    if (i >= seg) return;

    // i indexes 32-byte (float8) units; 4 units per 128-byte embedding row.
    int idx[NSEG];
    int id[NSEG];
#pragma unroll
    for (int s = 0; s < NSEG; s++) {
        idx[s] = i + s * seg;
        id[s]  = __ldg(&ids[idx[s] >> 2]);
    }

    U8 v[NSEG];
#pragma unroll
    for (int s = 0; s < NSEG; s++) {
        const void* src = table + (size_t)(unsigned)id[s] * 128 + (size_t)(idx[s] & 3) * 32;
        v[s] = ldg_table8(src);
    }

#pragma unroll
    for (int s = 0; s < NSEG; s++)
        stg_stream8(out + (size_t)idx[s] * 32, v[s]);
}

extern "C" void kernel_launch(void* const* d_in, const int* in_sizes, int n_in,
                              void* d_out, int out_size) {
    // Resolve inputs by element count (table: 32,000,000 f32; ids: 819,200).
    const int*  ids;
    const char* table;
    int n_rows;
    if (in_sizes[0] > in_sizes[1]) {
        table = (const char*)d_in[0];
        ids   = (const int*)d_in[1];
        n_rows = in_sizes[1];
    } else {
        ids   = (const int*)d_in[0];
        table = (const char*)d_in[1];
        n_rows = in_sizes[0];
    }

    char* out = (char*)d_out;
    int n8 = n_rows * 4;          // 32-byte units in output (divisible by NSEG)
    int seg = n8 / NSEG;
    int threads = 256;
    int blocks = (seg + threads - 1) / threads;
    embedding_gather_kernel<<<blocks, threads>>>(ids, table, out, seg);
}

// round 8
// speedup vs baseline: 1.0525x; 1.0525x over previous
#include <cuda_runtime.h>
#include <cuda_bf16.h>

// Embedding gather: out[i, :] = table[ids[i], :]
// ids: int32 [819200], table: f32 [1e6, 32] (~128 MB; touched ~72 MB, kept L2-resident),
// out: f32 [819200, 32]
//
//  - table loads: L2::evict_last policy (stay L2-resident across graph replays)
//                 + L1::no_allocate (random rows have ~0 L1 reuse; skip L1 fills)
//  - output stores: .cs streaming (write-once; don't evict the table)
//  - 4 independent row-gathers per thread (R5 structure — best warm-state config)

#define NSEG 4

__device__ __forceinline__ float4 ldg_table(const float4* p, unsigned long long pol) {
    float4 v;
    asm volatile("ld.global.nc.L1::no_allocate.L2::cache_hint.v4.f32 {%0,%1,%2,%3}, [%4], %5;"
                 : "=f"(v.x), "=f"(v.y), "=f"(v.z), "=f"(v.w)
                 : "l"(p), "l"(pol));
    return v;
}

__device__ __forceinline__ void stg_stream(float4* p, float4 v) {
    asm volatile("st.global.cs.v4.f32 [%0], {%1,%2,%3,%4};"
                 :: "l"(p), "f"(v.x), "f"(v.y), "f"(v.z), "f"(v.w)
                 : "memory");
}

__global__ void __launch_bounds__(256)
embedding_gather_kernel(const int* __restrict__ ids,
                        const float4* __restrict__ table4,
                        float4* __restrict__ out4,
                        int seg) {
    int i = blockIdx.x * blockDim.x + threadIdx.x;
    if (i >= seg) return;

    unsigned long long pol;
    asm volatile("createpolicy.fractional.L2::evict_last.b64 %0, 1.0;" : "=l"(pol));

    int idx[NSEG];
    int id[NSEG];
#pragma unroll
    for (int s = 0; s < NSEG; s++) {
        idx[s] = i + s * seg;
        id[s]  = __ldg(&ids[idx[s] >> 3]);
    }

    float4 v[NSEG];
#pragma unroll
    for (int s = 0; s < NSEG; s++)
        v[s] = ldg_table(&table4[(size_t)(unsigned)id[s] * 8 + (idx[s] & 7)], pol);

#pragma unroll
    for (int s = 0; s < NSEG; s++)
        stg_stream(&out4[idx[s]], v[s]);
}

extern "C" void kernel_launch(void* const* d_in, const int* in_sizes, int n_in,
                              void* d_out, int out_size) {
    // Resolve inputs by element count (table: 32,000,000 f32; ids: 819,200).
    const int*    ids;
    const float4* table;
    int n_rows;
    if (in_sizes[0] > in_sizes[1]) {
        table = (const float4*)d_in[0];
        ids   = (const int*)d_in[1];
        n_rows = in_sizes[1];
    } else {
        ids   = (const int*)d_in[0];
        table = (const float4*)d_in[1];
        n_rows = in_sizes[0];
    }

    float4* out = (float4*)d_out;
    int n4 = n_rows * 8;          // total float4 elements (divisible by NSEG)
    int seg = n4 / NSEG;
    int threads = 256;
    int blocks = (seg + threads - 1) / threads;
    embedding_gather_kernel<<<blocks, threads>>>(ids, table, out, seg);
}